// round 14
// baseline (speedup 1.0000x reference)
#include <cuda_runtime.h>
#include <cuda_bf16.h>
#include <cstdint>

// QuantumConvLayer: out[b, 2j]   = cos(q[2j]) * cos(pi * x[b, 2j])
//                   out[b, 2j+1] = out[b, 2j] * cos(q[2j+1] + pi * x[b, 2j+1])
// B = 4194304, N_QUBITS = 16. Streaming elementwise map.
//
// FINAL — best measured configuration (bench 81.5us, ncu 73.8-75.3us,
// DRAM 80.8-82.1%, rel_err 2.8e-7).
//
// Evidence ledger across the session:
//   R2  burst x4 front-batched ............ 82.0us bench / 73.8us ncu  <- this
//   R5  exact-tile (no predicates) ........ neutral (75.4us ncu)
//   R7  persistent + prefetch ............. REGRESSED (90.9us bench)
//   R9  burst x8 .......................... neutral (regs 60, occ 41%)
//   R11 L2 evict_last pinning ............. REGRESSED (84.5us bench)
//   R13 256-bit LDG/STG ................... neutral (82.2us bench)
// Conclusion: the kernel is bound by 512MB of mandatory L1<->LTS traffic at
// the path-independent LTS cap (~6.4 TB/s effective) = ~80us kernel + ~2us
// launch/ramp. The floor is reached; traffic is irreducible (fp32 contract).
//
// Structure: one thread per 4 float4s, front-batched LDG.128 x4 (MLP_p1=4),
// block-tiled so each warp load is 512B contiguous, streaming cache hints,
// single broadcast q load per thread ((base+k*256)&3 == base&3).

__global__ __launch_bounds__(256) void qconv_kernel(
    const float4* __restrict__ x4,
    const float4* __restrict__ q4,   // q_params viewed as 4x float4
    float4* __restrict__ out4,
    int n4)                          // total float4 elements = B*16/4
{
    const int UNROLL = 4;
    const int STRIDE = 256;          // blockDim.x
    int base = blockIdx.x * (STRIDE * UNROLL) + threadIdx.x;

    const float PI = 3.14159265358979323846f;

    // (base + k*256) & 3 == base & 3 for all k (256 % 4 == 0)
    float4 qv = q4[base & 3];

    // Front-batch all 4 independent 16B loads (MLP = 4 per thread)
    float4 xv[UNROLL];
#pragma unroll
    for (int k = 0; k < UNROLL; k++) {
        int idx = base + k * STRIDE;
        xv[k] = (idx < n4) ? __ldcs(x4 + idx) : make_float4(0.f, 0.f, 0.f, 0.f);
    }

    float4 rv[UNROLL];
#pragma unroll
    for (int k = 0; k < UNROLL; k++) {
        float z0 = __cosf(qv.x) * __cosf(PI * xv[k].x);
        float o0 = z0 * __cosf(qv.y + PI * xv[k].y);
        float z1 = __cosf(qv.z) * __cosf(PI * xv[k].z);
        float o1 = z1 * __cosf(qv.w + PI * xv[k].w);
        rv[k] = make_float4(z0, o0, z1, o1);
    }

#pragma unroll
    for (int k = 0; k < UNROLL; k++) {
        int idx = base + k * STRIDE;
        if (idx < n4) __stcs(out4 + idx, rv[k]);
    }
}

extern "C" void kernel_launch(void* const* d_in, const int* in_sizes, int n_in,
                              void* d_out, int out_size)
{
    const float4* x4 = (const float4*)d_in[0];      // x: [B, 16] float32
    const float4* q4 = (const float4*)d_in[1];      // q_params: [16] float32
    float4* out4 = (float4*)d_out;

    int n4 = out_size / 4;                           // 16,777,216
    int threads = 256;
    int per_block = threads * 4;                     // 1024 float4 per block
    int blocks = (n4 + per_block - 1) / per_block;   // 16,384

    qconv_kernel<<<blocks, threads>>>(x4, q4, out4, n4);
}

// round 15
// speedup vs baseline: 1.0090x; 1.0090x over previous
#include <cuda_runtime.h>
#include <cuda_bf16.h>
#include <cstdint>

// QuantumConvLayer: out[b, 2j]   = cos(q[2j]) * cos(pi * x[b, 2j])
//                   out[b, 2j+1] = out[b, 2j] * cos(q[2j+1] + pi * x[b, 2j+1])
// B = 4194304, N_QUBITS = 16. Streaming elementwise map.
//
// FINAL — best measured configuration. Identical source benched 81.5us (R12)
// and 82.7us (R14); ncu on the same binary read 75.3us/80.8% and
// 78.9us/76.9% DRAM — establishing a +/-1.5% run-to-run variance envelope.
//
// Evidence ledger:
//   R2  burst x4 front-batched ............ 82.0us bench / 73.8us ncu  <- this
//   R5  exact-tile (no predicates) ........ neutral
//   R7  persistent + prefetch ............. REGRESSED (90.9us)
//   R9  burst x8 .......................... neutral
//   R11 L2 evict_last pinning ............. REGRESSED (84.5us)
//   R13 256-bit LDG/STG ................... neutral (82.2us)
//   R14 identical resubmit of R12 ......... 82.7us (pure variance)
// Model: 512MB mandatory fp32 traffic (irreducible by contract) through the
// path-independent LTS cap (~6.4 TB/s effective) = ~80us kernel + ~2us
// replay overhead. Floor reached; no remaining change has positive EV.
//
// Structure: one thread per 4 float4s, front-batched LDG.128 x4 (MLP_p1=4),
// block-tiled so each warp load is 512B contiguous, streaming cache hints,
// single broadcast q load per thread ((base+k*256)&3 == base&3).

__global__ __launch_bounds__(256) void qconv_kernel(
    const float4* __restrict__ x4,
    const float4* __restrict__ q4,   // q_params viewed as 4x float4
    float4* __restrict__ out4,
    int n4)                          // total float4 elements = B*16/4
{
    const int UNROLL = 4;
    const int STRIDE = 256;          // blockDim.x
    int base = blockIdx.x * (STRIDE * UNROLL) + threadIdx.x;

    const float PI = 3.14159265358979323846f;

    // (base + k*256) & 3 == base & 3 for all k (256 % 4 == 0)
    float4 qv = q4[base & 3];

    // Front-batch all 4 independent 16B loads (MLP = 4 per thread)
    float4 xv[UNROLL];
#pragma unroll
    for (int k = 0; k < UNROLL; k++) {
        int idx = base + k * STRIDE;
        xv[k] = (idx < n4) ? __ldcs(x4 + idx) : make_float4(0.f, 0.f, 0.f, 0.f);
    }

    float4 rv[UNROLL];
#pragma unroll
    for (int k = 0; k < UNROLL; k++) {
        float z0 = __cosf(qv.x) * __cosf(PI * xv[k].x);
        float o0 = z0 * __cosf(qv.y + PI * xv[k].y);
        float z1 = __cosf(qv.z) * __cosf(PI * xv[k].z);
        float o1 = z1 * __cosf(qv.w + PI * xv[k].w);
        rv[k] = make_float4(z0, o0, z1, o1);
    }

#pragma unroll
    for (int k = 0; k < UNROLL; k++) {
        int idx = base + k * STRIDE;
        if (idx < n4) __stcs(out4 + idx, rv[k]);
    }
}

extern "C" void kernel_launch(void* const* d_in, const int* in_sizes, int n_in,
                              void* d_out, int out_size)
{
    const float4* x4 = (const float4*)d_in[0];      // x: [B, 16] float32
    const float4* q4 = (const float4*)d_in[1];      // q_params: [16] float32
    float4* out4 = (float4*)d_out;

    int n4 = out_size / 4;                           // 16,777,216
    int threads = 256;
    int per_block = threads * 4;                     // 1024 float4 per block
    int blocks = (n4 + per_block - 1) / per_block;   // 16,384

    qconv_kernel<<<blocks, threads>>>(x4, q4, out4, n4);
}